// round 9
// baseline (speedup 1.0000x reference)
#include <cuda_runtime.h>
#include <cuda_bf16.h>
#include <cstdint>

// Problem constants
#define BATCH 16
#define CCH   256        // channels
#define NPOS  1024       // H*W
#define NH    4
#define DH    64
#define GRP   8
#define CPG   32         // channels per group

typedef unsigned long long ull;

// ---------------------------------------------------------------------------
// Scratch (device globals; allocation is forbidden)
// ---------------------------------------------------------------------------
__device__ float g_xn [BATCH * CCH    * NPOS];   // 16 MB  group-normed x
__device__ float g_qkv[BATCH * 3*CCH  * NPOS];   // 48 MB  qkv projections
__device__ float g_o  [BATCH * CCH    * NPOS];   // 16 MB  attention output

// ---------------------------------------------------------------------------
// f32x2 helpers (sm_103a packed fp32 FMA — SASS FFMA2, PTX-only path)
// ---------------------------------------------------------------------------
__device__ __forceinline__ ull fma2(ull a, ull b, ull c) {
    ull d;
    asm("fma.rn.f32x2 %0, %1, %2, %3;" : "=l"(d) : "l"(a), "l"(b), "l"(c));
    return d;
}
__device__ __forceinline__ ull mul2(ull a, ull b) {
    ull d;
    asm("mul.rn.f32x2 %0, %1, %2;" : "=l"(d) : "l"(a), "l"(b));
    return d;
}
__device__ __forceinline__ ull pack2(float x, float y) {
    union { float2 f; ull u; } t; t.f = make_float2(x, y); return t.u;
}
__device__ __forceinline__ ull packbb(float x) { return pack2(x, x); }
__device__ __forceinline__ float2 unpack2(ull u) {
    union { float2 f; ull u; } t; t.u = u; return t.f;
}

// ---------------------------------------------------------------------------
// Kernel 1: GroupNorm.  One block per (b, g); 32768 elems per group.
// ---------------------------------------------------------------------------
__global__ __launch_bounds__(256)
void gn_kernel(const float* __restrict__ x,
               const float* __restrict__ w,
               const float* __restrict__ bia) {
    const int blk = blockIdx.x;
    const int b = blk >> 3, g = blk & 7;
    const size_t base = ((size_t)b * CCH + (size_t)g * CPG) * NPOS;
    const float4* xp = (const float4*)(x + base);
    float4* op = (float4*)(g_xn + base);
    const int tid = threadIdx.x;

    float s = 0.f, ss = 0.f;
    #pragma unroll 8
    for (int it = 0; it < 32; ++it) {
        float4 v = xp[it * 256 + tid];
        s  += v.x + v.y + v.z + v.w;
        ss += v.x*v.x + v.y*v.y + v.z*v.z + v.w*v.w;
    }
    __shared__ float rs[256], rq[256];
    rs[tid] = s; rq[tid] = ss;
    __syncthreads();
    for (int st = 128; st > 0; st >>= 1) {
        if (tid < st) { rs[tid] += rs[tid + st]; rq[tid] += rq[tid + st]; }
        __syncthreads();
    }
    __shared__ float csc[CPG], csh[CPG];
    if (tid < CPG) {
        const float invM = 1.f / 32768.f;
        float mean = rs[0] * invM;
        float var  = rq[0] * invM - mean * mean;
        float inv  = rsqrtf(var + 1e-5f);
        int c = g * CPG + tid;
        float sc = w[c] * inv;
        csc[tid] = sc;
        csh[tid] = bia[c] - mean * sc;
    }
    __syncthreads();
    #pragma unroll 8
    for (int it = 0; it < 32; ++it) {
        int idx = it * 256 + tid;
        int ch = idx >> 8;
        float4 v = xp[idx];
        float a = csc[ch], t = csh[ch];
        v.x = v.x * a + t;  v.y = v.y * a + t;
        v.z = v.z * a + t;  v.w = v.w * a + t;
        op[idx] = v;
    }
}

// ---------------------------------------------------------------------------
// Kernel 2: batched GEMM  out[b,m,n] = sum_c W[m,c]*X[b,c,n] + bias[m] (+res)
// BM=128 BN=128 BK=16, 256 threads (16x16), per-thread 8x8 tile via FFMA2.
// A-side SMEM reads are warp-broadcast; B-side conflict-free LDS.128.
// ---------------------------------------------------------------------------
#define WSTR 132   // Ws row stride (padded)

__global__ __launch_bounds__(256, 2)
void gemm_kernel(const float* __restrict__ W,
                 const float* __restrict__ bias,
                 const float* __restrict__ res,
                 float* __restrict__ out_ext,
                 int M, int phase) {
    const int Kd = CCH;
    const int Nd = NPOS;
    const float* X   = (phase == 0) ? g_xn  : g_o;
    float*       out = (phase == 0) ? g_qkv : out_ext;

    const int bx = blockIdx.x;
    const int by = blockIdx.y;
    const int b  = blockIdx.z;
    const int tid = threadIdx.x;
    const int tx = tid & 15, ty = tid >> 4;

    __shared__ __align__(16) float Ws[16 * WSTR];   // [k][m], padded
    __shared__ __align__(16) float Xs[16 * 128];    // [k][n]

    const float* Xb = X + (size_t)b * Kd * Nd;
    const int m0 = by * 128, n0 = bx * 128;

    ull acc[8][4];
    #pragma unroll
    for (int i = 0; i < 8; ++i)
        #pragma unroll
        for (int j = 0; j < 4; ++j) acc[i][j] = 0ull;

    for (int k0 = 0; k0 < Kd; k0 += 16) {
        // stage loads into registers
        float4 wv[2], xv[2];
        int rowA[2], kcA[2], kkX[2], n4X[2];
        #pragma unroll
        for (int r = 0; r < 2; ++r) {
            int idx = r * 256 + tid;
            rowA[r] = idx >> 2;  kcA[r] = (idx & 3) * 4;
            wv[r] = *(const float4*)(W + (size_t)(m0 + rowA[r]) * Kd + k0 + kcA[r]);
            kkX[r] = idx >> 5;   n4X[r] = (idx & 31) * 4;
            xv[r] = *(const float4*)(Xb + (size_t)(k0 + kkX[r]) * Nd + n0 + n4X[r]);
        }
        __syncthreads();
        #pragma unroll
        for (int r = 0; r < 2; ++r) {
            Ws[(kcA[r] + 0) * WSTR + rowA[r]] = wv[r].x;
            Ws[(kcA[r] + 1) * WSTR + rowA[r]] = wv[r].y;
            Ws[(kcA[r] + 2) * WSTR + rowA[r]] = wv[r].z;
            Ws[(kcA[r] + 3) * WSTR + rowA[r]] = wv[r].w;
            *(float4*)&Xs[kkX[r] * 128 + n4X[r]] = xv[r];
        }
        __syncthreads();

        #pragma unroll
        for (int kk = 0; kk < 16; ++kk) {
            float4 a0 = *(const float4*)&Ws[kk * WSTR + ty * 8];      // broadcast
            float4 a1 = *(const float4*)&Ws[kk * WSTR + ty * 8 + 4];  // broadcast
            ull am[8] = { packbb(a0.x), packbb(a0.y), packbb(a0.z), packbb(a0.w),
                          packbb(a1.x), packbb(a1.y), packbb(a1.z), packbb(a1.w) };
            ulonglong2 b0 = *(const ulonglong2*)&Xs[kk * 128 + tx * 8];
            ulonglong2 b1 = *(const ulonglong2*)&Xs[kk * 128 + tx * 8 + 4];
            ull bn[4] = { b0.x, b0.y, b1.x, b1.y };
            #pragma unroll
            for (int i = 0; i < 8; ++i)
                #pragma unroll
                for (int j = 0; j < 4; ++j)
                    acc[i][j] = fma2(am[i], bn[j], acc[i][j]);
        }
    }

    #pragma unroll
    for (int i = 0; i < 8; ++i) {
        const int m = m0 + ty * 8 + i;
        const float bv = bias[m];
        float r[8];
        #pragma unroll
        for (int j = 0; j < 4; ++j) {
            float2 f = unpack2(acc[i][j]);
            r[2*j]   = f.x + bv;
            r[2*j+1] = f.y + bv;
        }
        const size_t obase = ((size_t)b * M + m) * Nd + n0 + tx * 8;
        if (res) {
            float4 r0 = *(const float4*)(res + obase);
            float4 r1 = *(const float4*)(res + obase + 4);
            r[0] += r0.x; r[1] += r0.y; r[2] += r0.z; r[3] += r0.w;
            r[4] += r1.x; r[5] += r1.y; r[6] += r1.z; r[7] += r1.w;
        }
        *(float4*)(out + obase)     = make_float4(r[0], r[1], r[2], r[3]);
        *(float4*)(out + obase + 4) = make_float4(r[4], r[5], r[6], r[7]);
    }
}

// ---------------------------------------------------------------------------
// Kernel 3: flash attention, warp-shuffle softmax, register stats.
// Block = (b, h, 128-query tile); 256 threads.
// Lane mapping: kx = tid&15 spans keys/channels (in-warp), qy = tid>>4 queries.
// Per-query softmax reduction = 4x shfl_xor within the 16-lane group; running
// m/l kept redundantly in registers of all 16 lanes (identical values).
// ---------------------------------------------------------------------------
#define PSTR 132   // Ps row stride (padded)
#define VSTR 65    // Vs row stride (padded)
#define ATTN_SMEM_FLOATS (64*128 + 64*64 + 64*VSTR + 64*PSTR)
#define ATTN_SMEM_BYTES  (ATTN_SMEM_FLOATS * 4)

__global__ __launch_bounds__(256, 2)
void attn_kernel() {
    extern __shared__ __align__(16) float sm[];
    float* Qs = sm;                      // [64][128]
    float* Ks = Qs + 64 * 128;           // [64][64]
    float* Vs = Ks + 64 * 64;            // [64][VSTR]
    float* Ps = Vs + 64 * VSTR;          // [64][PSTR]

    const int b = blockIdx.z, h = blockIdx.y;
    const int q0 = blockIdx.x * 128;
    const int tid = threadIdx.x;
    const int kx = tid & 15;             // key / dh-channel group (in-warp)
    const int qy = tid >> 4;             // query group

    const float* qb = g_qkv + ((size_t)b * 3 * CCH + (size_t)h * DH) * NPOS;
    const float* kb = qb + (size_t)CCH * NPOS;
    const float* vb = qb + 2 * (size_t)CCH * NPOS;

    // Load Q tile (64 dh x 128 q), scaled by dh^-0.5
    #pragma unroll
    for (int r = 0; r < 8; ++r) {
        int idx = r * 256 + tid;
        int c = idx >> 5, q4 = (idx & 31) * 4;
        float4 v = *(const float4*)(qb + (size_t)c * NPOS + q0 + q4);
        v.x *= 0.125f; v.y *= 0.125f; v.z *= 0.125f; v.w *= 0.125f;
        *(float4*)&Qs[c * 128 + q4] = v;
    }

    float m[8], l[8];
    #pragma unroll
    for (int q = 0; q < 8; ++q) { m[q] = -1e30f; l[q] = 0.f; }
    ull O[4][4];
    #pragma unroll
    for (int i = 0; i < 4; ++i)
        #pragma unroll
        for (int j = 0; j < 4; ++j) O[i][j] = 0ull;

    for (int jt = 0; jt < 16; ++jt) {
        const float* kt = kb + jt * 64;
        const float* vt = vb + jt * 64;
        __syncthreads();                 // protect prior-tile Ks/Vs/Ps reads
        #pragma unroll
        for (int r = 0; r < 4; ++r) {
            int idx = r * 256 + tid;
            int c = idx >> 4, j4 = (idx & 15) * 4;
            *(float4*)&Ks[c * 64 + j4] = *(const float4*)(kt + (size_t)c * NPOS + j4);
            float4 vv = *(const float4*)(vt + (size_t)c * NPOS + j4);
            Vs[c * VSTR + j4 + 0] = vv.x; Vs[c * VSTR + j4 + 1] = vv.y;
            Vs[c * VSTR + j4 + 2] = vv.z; Vs[c * VSTR + j4 + 3] = vv.w;
        }
        __syncthreads();

        // --- QK^T: keys kx*4+i, query pairs qy*8+2jp ---
        ull S[4][4];
        #pragma unroll
        for (int i = 0; i < 4; ++i)
            #pragma unroll
            for (int j = 0; j < 4; ++j) S[i][j] = 0ull;

        #pragma unroll 8
        for (int c = 0; c < 64; ++c) {
            float4 k4 = *(const float4*)&Ks[c * 64 + kx * 4];           // 16 distinct, cf
            ull a0 = packbb(k4.x), a1 = packbb(k4.y);
            ull a2 = packbb(k4.z), a3 = packbb(k4.w);
            ulonglong2 q01 = *(const ulonglong2*)&Qs[c * 128 + qy * 8];     // broadcast
            ulonglong2 q23 = *(const ulonglong2*)&Qs[c * 128 + qy * 8 + 4]; // broadcast
            S[0][0] = fma2(a0, q01.x, S[0][0]); S[0][1] = fma2(a0, q01.y, S[0][1]);
            S[0][2] = fma2(a0, q23.x, S[0][2]); S[0][3] = fma2(a0, q23.y, S[0][3]);
            S[1][0] = fma2(a1, q01.x, S[1][0]); S[1][1] = fma2(a1, q01.y, S[1][1]);
            S[1][2] = fma2(a1, q23.x, S[1][2]); S[1][3] = fma2(a1, q23.y, S[1][3]);
            S[2][0] = fma2(a2, q01.x, S[2][0]); S[2][1] = fma2(a2, q01.y, S[2][1]);
            S[2][2] = fma2(a2, q23.x, S[2][2]); S[2][3] = fma2(a2, q23.y, S[2][3]);
            S[3][0] = fma2(a3, q01.x, S[3][0]); S[3][1] = fma2(a3, q01.y, S[3][1]);
            S[3][2] = fma2(a3, q23.x, S[3][2]); S[3][3] = fma2(a3, q23.y, S[3][3]);
        }

        // unpack scores
        float s[4][8];
        #pragma unroll
        for (int i = 0; i < 4; ++i)
            #pragma unroll
            for (int jp = 0; jp < 4; ++jp) {
                float2 f = unpack2(S[i][jp]);
                s[i][2*jp] = f.x; s[i][2*jp+1] = f.y;
            }

        // --- online softmax: in-warp reduction over keys ---
        float al[8];
        #pragma unroll
        for (int q = 0; q < 8; ++q) {
            float mq = fmaxf(fmaxf(s[0][q], s[1][q]), fmaxf(s[2][q], s[3][q]));
            mq = fmaxf(mq, __shfl_xor_sync(0xffffffffu, mq, 1));
            mq = fmaxf(mq, __shfl_xor_sync(0xffffffffu, mq, 2));
            mq = fmaxf(mq, __shfl_xor_sync(0xffffffffu, mq, 4));
            mq = fmaxf(mq, __shfl_xor_sync(0xffffffffu, mq, 8));
            float mn = fmaxf(m[q], mq);
            float a = __expf(m[q] - mn);
            float sum;
            {
                float e0 = __expf(s[0][q] - mn);
                float e1 = __expf(s[1][q] - mn);
                float e2 = __expf(s[2][q] - mn);
                float e3 = __expf(s[3][q] - mn);
                s[0][q] = e0; s[1][q] = e1; s[2][q] = e2; s[3][q] = e3;
                sum = (e0 + e1) + (e2 + e3);
            }
            sum += __shfl_xor_sync(0xffffffffu, sum, 1);
            sum += __shfl_xor_sync(0xffffffffu, sum, 2);
            sum += __shfl_xor_sync(0xffffffffu, sum, 4);
            sum += __shfl_xor_sync(0xffffffffu, sum, 8);
            l[q] = l[q] * a + sum;
            m[q] = mn;
            al[q] = a;
        }

        // rescale O
        ull a2v[4] = { pack2(al[0], al[1]), pack2(al[2], al[3]),
                       pack2(al[4], al[5]), pack2(al[6], al[7]) };
        #pragma unroll
        for (int i = 0; i < 4; ++i)
            #pragma unroll
            for (int jp = 0; jp < 4; ++jp)
                O[i][jp] = mul2(O[i][jp], a2v[jp]);

        // write P tile
        #pragma unroll
        for (int i = 0; i < 4; ++i) {
            float* row = &Ps[(kx * 4 + i) * PSTR + qy * 8];
            *(float4*)row       = make_float4(s[i][0], s[i][1], s[i][2], s[i][3]);
            *(float4*)(row + 4) = make_float4(s[i][4], s[i][5], s[i][6], s[i][7]);
        }
        __syncthreads();

        // --- O += V @ P  (channels kx*4+i) ---
        #pragma unroll 8
        for (int j = 0; j < 64; ++j) {
            ull w0 = packbb(Vs[(kx * 4 + 0) * VSTR + j]);
            ull w1 = packbb(Vs[(kx * 4 + 1) * VSTR + j]);
            ull w2 = packbb(Vs[(kx * 4 + 2) * VSTR + j]);
            ull w3 = packbb(Vs[(kx * 4 + 3) * VSTR + j]);
            ulonglong2 p01 = *(const ulonglong2*)&Ps[j * PSTR + qy * 8];     // broadcast
            ulonglong2 p23 = *(const ulonglong2*)&Ps[j * PSTR + qy * 8 + 4]; // broadcast
            O[0][0] = fma2(w0, p01.x, O[0][0]); O[0][1] = fma2(w0, p01.y, O[0][1]);
            O[0][2] = fma2(w0, p23.x, O[0][2]); O[0][3] = fma2(w0, p23.y, O[0][3]);
            O[1][0] = fma2(w1, p01.x, O[1][0]); O[1][1] = fma2(w1, p01.y, O[1][1]);
            O[1][2] = fma2(w1, p23.x, O[1][2]); O[1][3] = fma2(w1, p23.y, O[1][3]);
            O[2][0] = fma2(w2, p01.x, O[2][0]); O[2][1] = fma2(w2, p01.y, O[2][1]);
            O[2][2] = fma2(w2, p23.x, O[2][2]); O[2][3] = fma2(w2, p23.y, O[2][3]);
            O[3][0] = fma2(w3, p01.x, O[3][0]); O[3][1] = fma2(w3, p01.y, O[3][1]);
            O[3][2] = fma2(w3, p23.x, O[3][2]); O[3][3] = fma2(w3, p23.y, O[3][3]);
        }
    }

    // epilogue: normalize by 1/l and store
    float rl[8];
    #pragma unroll
    for (int q = 0; q < 8; ++q) rl[q] = 1.f / l[q];
    float* ob = g_o + ((size_t)b * CCH + (size_t)h * DH) * NPOS + q0;
    #pragma unroll
    for (int i = 0; i < 4; ++i) {
        float2 f0 = unpack2(O[i][0]), f1 = unpack2(O[i][1]);
        float2 f2 = unpack2(O[i][2]), f3 = unpack2(O[i][3]);
        float* row = ob + (size_t)(kx * 4 + i) * NPOS + qy * 8;
        *(float4*)row       = make_float4(f0.x * rl[0], f0.y * rl[1], f1.x * rl[2], f1.y * rl[3]);
        *(float4*)(row + 4) = make_float4(f2.x * rl[4], f2.y * rl[5], f3.x * rl[6], f3.y * rl[7]);
    }
}

// ---------------------------------------------------------------------------
// Launch
// ---------------------------------------------------------------------------
extern "C" void kernel_launch(void* const* d_in, const int* in_sizes, int n_in,
                              void* d_out, int out_size) {
    const float* x        = (const float*)d_in[0];
    const float* n_weight = (const float*)d_in[1];
    const float* n_bias   = (const float*)d_in[2];
    const float* qkv_w    = (const float*)d_in[3];
    const float* qkv_b    = (const float*)d_in[4];
    const float* p_w      = (const float*)d_in[5];
    const float* p_b      = (const float*)d_in[6];
    float* out = (float*)d_out;

    static int smem_set = 0;
    if (!smem_set) {
        cudaFuncSetAttribute(attn_kernel,
                             cudaFuncAttributeMaxDynamicSharedMemorySize,
                             ATTN_SMEM_BYTES);
        smem_set = 1;
    }

    // 1) GroupNorm -> g_xn
    gn_kernel<<<BATCH * GRP, 256>>>(x, n_weight, n_bias);

    // 2) QKV GEMM: g_qkv = qkv_w @ g_xn + qkv_b   (M=768, 6 m-tiles)
    gemm_kernel<<<dim3(8, 6, BATCH), 256>>>(qkv_w, qkv_b, nullptr, nullptr, 768, 0);

    // 3) Attention: g_qkv -> g_o
    attn_kernel<<<dim3(8, NH, BATCH), 256, ATTN_SMEM_BYTES>>>();

    // 4) Proj + bias + residual: out = x + p_w @ g_o + p_b   (M=256, 2 m-tiles)
    gemm_kernel<<<dim3(8, 2, BATCH), 256>>>(p_w, p_b, x, out, 256, 1);
}

// round 15
// speedup vs baseline: 1.2234x; 1.2234x over previous
#include <cuda_runtime.h>
#include <cuda_bf16.h>
#include <cstdint>

// Problem constants
#define BATCH 16
#define CCH   256        // channels
#define NPOS  1024       // H*W
#define NH    4
#define DH    64
#define GRP   8
#define CPG   32         // channels per group

typedef unsigned long long ull;

// ---------------------------------------------------------------------------
// Scratch (device globals; allocation is forbidden)
// ---------------------------------------------------------------------------
__device__ float         g_qkv [BATCH * 3*CCH * NPOS];     // 48 MB qkv fp32 [b][768][n]
__device__ __nv_bfloat16 g_xnth[BATCH * NPOS * CCH];       // 8 MB  xn^T hi  [b][n][k]
__device__ __nv_bfloat16 g_xntl[BATCH * NPOS * CCH];       // 8 MB  xn^T lo
__device__ __nv_bfloat16 g_oth [BATCH * NPOS * CCH];       // 8 MB  o^T hi   [b][n][k]
__device__ __nv_bfloat16 g_otl [BATCH * NPOS * CCH];       // 8 MB  o^T lo
__device__ __nv_bfloat16 g_wh  [(3*CCH + CCH) * CCH];      // qkv_w rows 0-767, p_w rows 768-1023
__device__ __nv_bfloat16 g_wl  [(3*CCH + CCH) * CCH];

// ---------------------------------------------------------------------------
// f32x2 helpers (FFMA2 path, used by attention)
// ---------------------------------------------------------------------------
__device__ __forceinline__ ull fma2(ull a, ull b, ull c) {
    ull d;
    asm("fma.rn.f32x2 %0, %1, %2, %3;" : "=l"(d) : "l"(a), "l"(b), "l"(c));
    return d;
}
__device__ __forceinline__ ull mul2(ull a, ull b) {
    ull d;
    asm("mul.rn.f32x2 %0, %1, %2;" : "=l"(d) : "l"(a), "l"(b));
    return d;
}
__device__ __forceinline__ ull pack2(float x, float y) {
    union { float2 f; ull u; } t; t.f = make_float2(x, y); return t.u;
}
__device__ __forceinline__ ull packbb(float x) { return pack2(x, x); }
__device__ __forceinline__ float2 unpack2(ull u) {
    union { float2 f; ull u; } t; t.u = u; return t.f;
}

__device__ __forceinline__ uint32_t smem_u32(const void* p) {
    uint32_t a;
    asm("{ .reg .u64 t; cvta.to.shared.u64 t, %1; cvt.u32.u64 %0, t; }"
        : "=r"(a) : "l"(p));
    return a;
}

// ---------------------------------------------------------------------------
// mma.sync / ldmatrix (baseline PTX — valid on compute_103)
// ---------------------------------------------------------------------------
#define LDSM_X4(r, addr) \
    asm volatile("ldmatrix.sync.aligned.m8n8.x4.shared.b16 {%0,%1,%2,%3}, [%4];" \
        : "=r"((r)[0]), "=r"((r)[1]), "=r"((r)[2]), "=r"((r)[3]) : "r"(addr))
#define LDSM_X2(r, addr) \
    asm volatile("ldmatrix.sync.aligned.m8n8.x2.shared.b16 {%0,%1}, [%2];" \
        : "=r"((r)[0]), "=r"((r)[1]) : "r"(addr))
#define MMA_BF16(c, a, bb) \
    asm volatile("mma.sync.aligned.m16n8k16.row.col.f32.bf16.bf16.f32 " \
        "{%0,%1,%2,%3}, {%4,%5,%6,%7}, {%8,%9}, {%0,%1,%2,%3};" \
        : "+f"((c)[0]), "+f"((c)[1]), "+f"((c)[2]), "+f"((c)[3]) \
        : "r"((a)[0]), "r"((a)[1]), "r"((a)[2]), "r"((a)[3]), \
          "r"((bb)[0]), "r"((bb)[1]))

__device__ __forceinline__ void split_bf16(float v, __nv_bfloat16& hi, __nv_bfloat16& lo) {
    hi = __float2bfloat16(v);
    lo = __float2bfloat16(v - __bfloat162float(hi));
}

// ---------------------------------------------------------------------------
// Kernel 0: weight split-bf16 prep.  1024x256 floats -> hi/lo planes.
// ---------------------------------------------------------------------------
__global__ __launch_bounds__(256)
void wprep_kernel(const float* __restrict__ qkvw, const float* __restrict__ pw) {
    int i = blockIdx.x * 256 + threadIdx.x;     // 0 .. 262143
    float v = (i < 768 * 256) ? qkvw[i] : pw[i - 768 * 256];
    __nv_bfloat16 hi, lo;
    split_bf16(v, hi, lo);
    g_wh[i] = hi;
    g_wl[i] = lo;
}

// ---------------------------------------------------------------------------
// Kernel 1: GroupNorm -> transposed split-bf16 planes g_xnT[b][n][k].
// One block per (b, g).
// ---------------------------------------------------------------------------
__global__ __launch_bounds__(256)
void gn_kernel(const float* __restrict__ x,
               const float* __restrict__ w,
               const float* __restrict__ bia) {
    const int blk = blockIdx.x;
    const int b = blk >> 3, g = blk & 7;
    const size_t base = ((size_t)b * CCH + (size_t)g * CPG) * NPOS;
    const float4* xp = (const float4*)(x + base);
    const int tid = threadIdx.x;

    float s = 0.f, ss = 0.f;
    #pragma unroll 8
    for (int it = 0; it < 32; ++it) {
        float4 v = xp[it * 256 + tid];
        s  += v.x + v.y + v.z + v.w;
        ss += v.x*v.x + v.y*v.y + v.z*v.z + v.w*v.w;
    }
    __shared__ float rs[256], rq[256];
    rs[tid] = s; rq[tid] = ss;
    __syncthreads();
    for (int st = 128; st > 0; st >>= 1) {
        if (tid < st) { rs[tid] += rs[tid + st]; rq[tid] += rq[tid + st]; }
        __syncthreads();
    }
    __shared__ float csc[CPG], csh[CPG];
    if (tid < CPG) {
        const float invM = 1.f / 32768.f;
        float mean = rs[0] * invM;
        float var  = rq[0] * invM - mean * mean;
        float inv  = rsqrtf(var + 1e-5f);
        int c = g * CPG + tid;
        float sc = w[c] * inv;
        csc[tid] = sc;
        csh[tid] = bia[c] - mean * sc;
    }
    __syncthreads();

    // transpose + split-bf16 emit: 8 n-blocks of 128
    __shared__ float T[32][129];
    __nv_bfloat16* oh = g_xnth + (size_t)b * NPOS * CCH + g * CPG;
    __nv_bfloat16* ol = g_xntl + (size_t)b * NPOS * CCH + g * CPG;

    for (int nb = 0; nb < 8; ++nb) {
        __syncthreads();            // protect prior T reads
        #pragma unroll
        for (int r = 0; r < 4; ++r) {
            int lin = r * 256 + tid;
            int c = lin >> 5, n4 = (lin & 31) * 4;
            float4 v = *(const float4*)(x + base + (size_t)c * NPOS + nb * 128 + n4);
            float a = csc[c], t = csh[c];
            T[c][n4 + 0] = v.x * a + t;  T[c][n4 + 1] = v.y * a + t;
            T[c][n4 + 2] = v.z * a + t;  T[c][n4 + 3] = v.w * a + t;
        }
        __syncthreads();
        int n = tid >> 1, kh = (tid & 1) * 16;
        union { __nv_bfloat16 h[16]; uint4 u[2]; } uh, ulo;
        #pragma unroll
        for (int k = 0; k < 16; ++k) {
            __nv_bfloat16 hi, lo;
            split_bf16(T[kh + k][n], hi, lo);
            uh.h[k] = hi; ulo.h[k] = lo;
        }
        size_t doff = (size_t)(nb * 128 + n) * CCH + kh;
        *(uint4*)(oh + doff)     = uh.u[0];
        *(uint4*)(oh + doff + 8) = uh.u[1];
        *(uint4*)(ol + doff)     = ulo.u[0];
        *(uint4*)(ol + doff + 8) = ulo.u[1];
    }
}

// ---------------------------------------------------------------------------
// Kernel 2: split-bf16 GEMM on mma.sync (m16n8k16 HMMA).
// D[m,n] = sum_k (Whi+Wlo)[m,k] * (Bhi+Blo)[n,k]  (3 MMA terms, fp32 accum)
// CTA tile 128x128, 8 warps (2m x 4n), warp tile 64x32 = 4x4 fragments.
// K=256 in 4 SMEM chunks of 64. Rows padded to 72 bf16 (144B) so each
// ldmatrix 8-row phase hits distinct banks.
// phase 0: B = g_xnT, out = g_qkv, W rows 0-767.
// phase 1: B = g_oT,  out = out_ext (+res), W rows 768-1023.
// ---------------------------------------------------------------------------
#define GM_PAD   72
#define GM_PLANE (128 * GM_PAD)             // bf16 elems per plane
#define GM_SMEM_BYTES (4 * GM_PLANE * 2)    // 73728 B

__global__ __launch_bounds__(256, 2)
void gemm_mma(const float* __restrict__ bias,
              const float* __restrict__ res,
              float* __restrict__ out_ext,
              int Mtot, int phase) {
    extern __shared__ __align__(16) __nv_bfloat16 gsm[];
    __nv_bfloat16* Ah = gsm;
    __nv_bfloat16* Al = gsm + GM_PLANE;
    __nv_bfloat16* Bh = gsm + 2 * GM_PLANE;
    __nv_bfloat16* Bl = gsm + 3 * GM_PLANE;

    const int tid = threadIdx.x, lane = tid & 31, wid = tid >> 5;
    const int wm = wid >> 2, wn = wid & 3;          // warp grid 2(m) x 4(n)
    const int b = blockIdx.z;
    const int n0 = blockIdx.x * 128, m0 = blockIdx.y * 128;
    const int w_off = (phase == 0) ? 0 : 768;

    const __nv_bfloat16* AgH = g_wh + (size_t)(w_off + m0) * CCH;
    const __nv_bfloat16* AgL = g_wl + (size_t)(w_off + m0) * CCH;
    const __nv_bfloat16* BgH = ((phase == 0) ? g_xnth : g_oth) + ((size_t)b * NPOS + n0) * CCH;
    const __nv_bfloat16* BgL = ((phase == 0) ? g_xntl : g_otl) + ((size_t)b * NPOS + n0) * CCH;
    float* out = (phase == 0) ? g_qkv : out_ext;

    float acc[4][4][4];
    #pragma unroll
    for (int i = 0; i < 4; ++i)
        #pragma unroll
        for (int j = 0; j < 4; ++j)
            #pragma unroll
            for (int k = 0; k < 4; ++k) acc[i][j][k] = 0.f;

    // per-lane ldmatrix base addresses
    const int aRow = (lane & 7) + ((lane >> 3) & 1) * 8;
    const int aCol = (lane >> 4) * 8;
    const uint32_t aBase = smem_u32(Ah) + (uint32_t)(((wm * 64 + aRow) * GM_PAD + aCol) * 2);
    const int bRow = lane & 7;
    const int bCol = ((lane >> 3) & 1) * 8;
    const uint32_t bBase = smem_u32(Bh) + (uint32_t)(((wn * 32 + bRow) * GM_PAD + bCol) * 2);

    for (int kc = 0; kc < 4; ++kc) {
        __syncthreads();                    // previous chunk's compute done
        #pragma unroll
        for (int it = 0; it < 4; ++it) {
            int slot = it * 256 + tid;      // 1024 slots: 128 rows x 8 segments
            int r = slot >> 3, sgm = slot & 7;
            size_t go = (size_t)r * CCH + kc * 64 + sgm * 8;
            uint4 vah = *(const uint4*)(AgH + go);
            uint4 val = *(const uint4*)(AgL + go);
            uint4 vbh = *(const uint4*)(BgH + go);
            uint4 vbl = *(const uint4*)(BgL + go);
            int so = r * GM_PAD + sgm * 8;
            *(uint4*)(Ah + so) = vah;
            *(uint4*)(Al + so) = val;
            *(uint4*)(Bh + so) = vbh;
            *(uint4*)(Bl + so) = vbl;
        }
        __syncthreads();

        #pragma unroll
        for (int ks = 0; ks < 4; ++ks) {
            uint32_t ah[4][4], al[4][4];
            #pragma unroll
            for (int mt = 0; mt < 4; ++mt) {
                uint32_t adr = aBase + (uint32_t)((mt * 16 * GM_PAD + ks * 16) * 2);
                LDSM_X4(ah[mt], adr);
                LDSM_X4(al[mt], adr + GM_PLANE * 2);
            }
            #pragma unroll
            for (int nt = 0; nt < 4; ++nt) {
                uint32_t bdr = bBase + (uint32_t)((nt * 8 * GM_PAD + ks * 16) * 2);
                uint32_t bhf[2], blf[2];
                LDSM_X2(bhf, bdr);
                LDSM_X2(blf, bdr + GM_PLANE * 2);
                #pragma unroll
                for (int mt = 0; mt < 4; ++mt) {
                    MMA_BF16(acc[mt][nt], ah[mt], bhf);
                    MMA_BF16(acc[mt][nt], ah[mt], blf);
                    MMA_BF16(acc[mt][nt], al[mt], bhf);
                }
            }
        }
    }

    // epilogue: direct stores; c0,c1 -> (row g, col 2q..2q+1); c2,c3 -> row g+8
    const int g = lane >> 2, q2 = (lane & 3) * 2;
    #pragma unroll
    for (int mt = 0; mt < 4; ++mt) {
        const int r0 = m0 + wm * 64 + mt * 16 + g;
        const float bv0 = bias[r0];
        const float bv1 = bias[r0 + 8];
        #pragma unroll
        for (int nt = 0; nt < 4; ++nt) {
            const int col = n0 + wn * 32 + nt * 8 + q2;
            const size_t o0 = ((size_t)b * Mtot + r0) * NPOS + col;
            const size_t o1 = o0 + 8 * (size_t)NPOS;
            float2 v0 = make_float2(acc[mt][nt][0] + bv0, acc[mt][nt][1] + bv0);
            float2 v1 = make_float2(acc[mt][nt][2] + bv1, acc[mt][nt][3] + bv1);
            if (res) {
                float2 rr0 = *(const float2*)(res + o0);
                float2 rr1 = *(const float2*)(res + o1);
                v0.x += rr0.x; v0.y += rr0.y;
                v1.x += rr1.x; v1.y += rr1.y;
            }
            *(float2*)(out + o0) = v0;
            *(float2*)(out + o1) = v1;
        }
    }
}

// ---------------------------------------------------------------------------
// Kernel 3: flash attention (FFMA2), mainloop unchanged; epilogue writes
// transposed split-bf16 planes g_oT[b][n][k] for the proj GEMM.
// ---------------------------------------------------------------------------
#define PSTR 132   // Ps row stride (padded); Ps also reused as [128][66]
#define VSTR 65    // Vs row stride (padded)
#define ATTN_SMEM_FLOATS (64*128 + 64*64 + 64*VSTR + 64*PSTR)
#define ATTN_SMEM_BYTES  (ATTN_SMEM_FLOATS * 4)

__global__ __launch_bounds__(256, 2)
void attn_kernel() {
    extern __shared__ __align__(16) float sm[];
    float* Qs = sm;                      // [64][128]
    float* Ks = Qs + 64 * 128;           // [64][64]
    float* Vs = Ks + 64 * 64;            // [64][VSTR]
    float* Ps = Vs + 64 * VSTR;          // [64][PSTR]

    const int b = blockIdx.z, h = blockIdx.y;
    const int q0 = blockIdx.x * 128;
    const int tid = threadIdx.x;
    const int kx = tid & 15;             // key / dh-channel group (in-warp)
    const int qy = tid >> 4;             // query group

    const float* qb = g_qkv + ((size_t)b * 3 * CCH + (size_t)h * DH) * NPOS;
    const float* kb = qb + (size_t)CCH * NPOS;
    const float* vb = qb + 2 * (size_t)CCH * NPOS;

    #pragma unroll
    for (int r = 0; r < 8; ++r) {
        int idx = r * 256 + tid;
        int c = idx >> 5, q4 = (idx & 31) * 4;
        float4 v = *(const float4*)(qb + (size_t)c * NPOS + q0 + q4);
        v.x *= 0.125f; v.y *= 0.125f; v.z *= 0.125f; v.w *= 0.125f;
        *(float4*)&Qs[c * 128 + q4] = v;
    }

    float m[8], l[8];
    #pragma unroll
    for (int q = 0; q < 8; ++q) { m[q] = -1e30f; l[q] = 0.f; }
    ull O[4][4];
    #pragma unroll
    for (int i = 0; i < 4; ++i)
        #pragma unroll
        for (int j = 0; j < 4; ++j) O[i][j] = 0ull;

    for (int jt = 0; jt < 16; ++jt) {
        const float* kt = kb + jt * 64;
        const float* vt = vb + jt * 64;
        __syncthreads();
        #pragma unroll
        for (int r = 0; r < 4; ++r) {
            int idx = r * 256 + tid;
            int c = idx >> 4, j4 = (idx & 15) * 4;
            *(float4*)&Ks[c * 64 + j4] = *(const float4*)(kt + (size_t)c * NPOS + j4);
            float4 vv = *(const float4*)(vt + (size_t)c * NPOS + j4);
            Vs[c * VSTR + j4 + 0] = vv.x; Vs[c * VSTR + j4 + 1] = vv.y;
            Vs[c * VSTR + j4 + 2] = vv.z; Vs[c * VSTR + j4 + 3] = vv.w;
        }
        __syncthreads();

        ull S[4][4];
        #pragma unroll
        for (int i = 0; i < 4; ++i)
            #pragma unroll
            for (int j = 0; j < 4; ++j) S[i][j] = 0ull;

        #pragma unroll 8
        for (int c = 0; c < 64; ++c) {
            float4 k4 = *(const float4*)&Ks[c * 64 + kx * 4];
            ull a0 = packbb(k4.x), a1 = packbb(k4.y);
            ull a2 = packbb(k4.z), a3 = packbb(k4.w);
            ulonglong2 q01 = *(const ulonglong2*)&Qs[c * 128 + qy * 8];
            ulonglong2 q23 = *(const ulonglong2*)&Qs[c * 128 + qy * 8 + 4];
            S[0][0] = fma2(a0, q01.x, S[0][0]); S[0][1] = fma2(a0, q01.y, S[0][1]);
            S[0][2] = fma2(a0, q23.x, S[0][2]); S[0][3] = fma2(a0, q23.y, S[0][3]);
            S[1][0] = fma2(a1, q01.x, S[1][0]); S[1][1] = fma2(a1, q01.y, S[1][1]);
            S[1][2] = fma2(a1, q23.x, S[1][2]); S[1][3] = fma2(a1, q23.y, S[1][3]);
            S[2][0] = fma2(a2, q01.x, S[2][0]); S[2][1] = fma2(a2, q01.y, S[2][1]);
            S[2][2] = fma2(a2, q23.x, S[2][2]); S[2][3] = fma2(a2, q23.y, S[2][3]);
            S[3][0] = fma2(a3, q01.x, S[3][0]); S[3][1] = fma2(a3, q01.y, S[3][1]);
            S[3][2] = fma2(a3, q23.x, S[3][2]); S[3][3] = fma2(a3, q23.y, S[3][3]);
        }

        float s[4][8];
        #pragma unroll
        for (int i = 0; i < 4; ++i)
            #pragma unroll
            for (int jp = 0; jp < 4; ++jp) {
                float2 f = unpack2(S[i][jp]);
                s[i][2*jp] = f.x; s[i][2*jp+1] = f.y;
            }

        float al[8];
        #pragma unroll
        for (int q = 0; q < 8; ++q) {
            float mq = fmaxf(fmaxf(s[0][q], s[1][q]), fmaxf(s[2][q], s[3][q]));
            mq = fmaxf(mq, __shfl_xor_sync(0xffffffffu, mq, 1));
            mq = fmaxf(mq, __shfl_xor_sync(0xffffffffu, mq, 2));
            mq = fmaxf(mq, __shfl_xor_sync(0xffffffffu, mq, 4));
            mq = fmaxf(mq, __shfl_xor_sync(0xffffffffu, mq, 8));
            float mn = fmaxf(m[q], mq);
            float a = __expf(m[q] - mn);
            float e0 = __expf(s[0][q] - mn);
            float e1 = __expf(s[1][q] - mn);
            float e2 = __expf(s[2][q] - mn);
            float e3 = __expf(s[3][q] - mn);
            s[0][q] = e0; s[1][q] = e1; s[2][q] = e2; s[3][q] = e3;
            float sum = (e0 + e1) + (e2 + e3);
            sum += __shfl_xor_sync(0xffffffffu, sum, 1);
            sum += __shfl_xor_sync(0xffffffffu, sum, 2);
            sum += __shfl_xor_sync(0xffffffffu, sum, 4);
            sum += __shfl_xor_sync(0xffffffffu, sum, 8);
            l[q] = l[q] * a + sum;
            m[q] = mn;
            al[q] = a;
        }

        ull a2v[4] = { pack2(al[0], al[1]), pack2(al[2], al[3]),
                       pack2(al[4], al[5]), pack2(al[6], al[7]) };
        #pragma unroll
        for (int i = 0; i < 4; ++i)
            #pragma unroll
            for (int jp = 0; jp < 4; ++jp)
                O[i][jp] = mul2(O[i][jp], a2v[jp]);

        #pragma unroll
        for (int i = 0; i < 4; ++i) {
            float* row = &Ps[(kx * 4 + i) * PSTR + qy * 8];
            *(float4*)row       = make_float4(s[i][0], s[i][1], s[i][2], s[i][3]);
            *(float4*)(row + 4) = make_float4(s[i][4], s[i][5], s[i][6], s[i][7]);
        }
        __syncthreads();

        #pragma unroll 8
        for (int j = 0; j < 64; ++j) {
            ull w0 = packbb(Vs[(kx * 4 + 0) * VSTR + j]);
            ull w1 = packbb(Vs[(kx * 4 + 1) * VSTR + j]);
            ull w2 = packbb(Vs[(kx * 4 + 2) * VSTR + j]);
            ull w3 = packbb(Vs[(kx * 4 + 3) * VSTR + j]);
            ulonglong2 p01 = *(const ulonglong2*)&Ps[j * PSTR + qy * 8];
            ulonglong2 p23 = *(const ulonglong2*)&Ps[j * PSTR + qy * 8 + 4];
            O[0][0] = fma2(w0, p01.x, O[0][0]); O[0][1] = fma2(w0, p01.y, O[0][1]);
            O[0][2] = fma2(w0, p23.x, O[0][2]); O[0][3] = fma2(w0, p23.y, O[0][3]);
            O[1][0] = fma2(w1, p01.x, O[1][0]); O[1][1] = fma2(w1, p01.y, O[1][1]);
            O[1][2] = fma2(w1, p23.x, O[1][2]); O[1][3] = fma2(w1, p23.y, O[1][3]);
            O[2][0] = fma2(w2, p01.x, O[2][0]); O[2][1] = fma2(w2, p01.y, O[2][1]);
            O[2][2] = fma2(w2, p23.x, O[2][2]); O[2][3] = fma2(w2, p23.y, O[2][3]);
            O[3][0] = fma2(w3, p01.x, O[3][0]); O[3][1] = fma2(w3, p01.y, O[3][1]);
            O[3][2] = fma2(w3, p23.x, O[3][2]); O[3][3] = fma2(w3, p23.y, O[3][3]);
        }
    }

    // epilogue: normalize, stage transposed in SMEM, emit split-bf16 planes
    float rl[8];
    #pragma unroll
    for (int q = 0; q < 8; ++q) rl[q] = 1.f / l[q];

    __syncthreads();                       // Ps free for reuse as [128][66]
    float* Od = Ps;
    #pragma unroll
    for (int i = 0; i < 4; ++i) {
        float2 f0 = unpack2(O[i][0]), f1 = unpack2(O[i][1]);
        float2 f2 = unpack2(O[i][2]), f3 = unpack2(O[i][3]);
        float vals[8] = { f0.x * rl[0], f0.y * rl[1], f1.x * rl[2], f1.y * rl[3],
                          f2.x * rl[4], f2.y * rl[5], f3.x * rl[6], f3.y * rl[7] };
        #pragma unroll
        for (int jq = 0; jq < 8; ++jq)
            Od[(qy * 8 + jq) * 66 + kx * 4 + i] = vals[jq];
    }
    __syncthreads();
    {
        int q = tid >> 1, ch = (tid & 1) * 32;
        union { __nv_bfloat16 hh[32]; uint4 u[4]; } uh, ulo;
        #pragma unroll
        for (int j = 0; j < 32; ++j) {
            __nv_bfloat16 hi, lo;
            split_bf16(Od[q * 66 + ch + j], hi, lo);
            uh.hh[j] = hi; ulo.hh[j] = lo;
        }
        size_t doff = ((size_t)b * NPOS + q0 + q) * CCH + h * DH + ch;
        *(uint4*)(g_oth + doff)      = uh.u[0];
        *(uint4*)(g_oth + doff + 8)  = uh.u[1];
        *(uint4*)(g_oth + doff + 16) = uh.u[2];
        *(uint4*)(g_oth + doff + 24) = uh.u[3];
        *(uint4*)(g_otl + doff)      = ulo.u[0];
        *(uint4*)(g_otl + doff + 8)  = ulo.u[1];
        *(uint4*)(g_otl + doff + 16) = ulo.u[2];
        *(uint4*)(g_otl + doff + 24) = ulo.u[3];
    }
}

// ---------------------------------------------------------------------------
// Launch
// ---------------------------------------------------------------------------
extern "C" void kernel_launch(void* const* d_in, const int* in_sizes, int n_in,
                              void* d_out, int out_size) {
    const float* x        = (const float*)d_in[0];
    const float* n_weight = (const float*)d_in[1];
    const float* n_bias   = (const float*)d_in[2];
    const float* qkv_w    = (const float*)d_in[3];
    const float* qkv_b    = (const float*)d_in[4];
    const float* p_w      = (const float*)d_in[5];
    const float* p_b      = (const float*)d_in[6];
    float* out = (float*)d_out;

    cudaFuncSetAttribute(attn_kernel, cudaFuncAttributeMaxDynamicSharedMemorySize,
                         ATTN_SMEM_BYTES);
    cudaFuncSetAttribute(gemm_mma, cudaFuncAttributeMaxDynamicSharedMemorySize,
                         GM_SMEM_BYTES);

    // 0) split weights to bf16 hi/lo planes
    wprep_kernel<<<1024, 256>>>(qkv_w, p_w);

    // 1) GroupNorm -> transposed bf16 hi/lo planes
    gn_kernel<<<BATCH * GRP, 256>>>(x, n_weight, n_bias);

    // 2) QKV GEMM (mma.sync split-bf16): g_qkv = qkv_w @ xn + qkv_b
    gemm_mma<<<dim3(8, 6, BATCH), 256, GM_SMEM_BYTES>>>(qkv_b, nullptr, nullptr, 768, 0);

    // 3) Attention: g_qkv -> g_oT (split-bf16, transposed)
    attn_kernel<<<dim3(8, NH, BATCH), 256, ATTN_SMEM_BYTES>>>();

    // 4) Proj GEMM (mma.sync) + bias + residual: out = x + p_w @ o + p_b
    gemm_mma<<<dim3(8, 2, BATCH), 256, GM_SMEM_BYTES>>>(p_b, x, out, 256, 1);
}